// round 8
// baseline (speedup 1.0000x reference)
#include <cuda_runtime.h>

// WeightedDistanceTransform — 2-kernel pipeline with CGA-fused pass B.
// k1: bitmask pack (ballot) -> 1-bit mask scratch (2 KB/slice, L2-hot)
// k2: cluster of 8 CTAs = 1 slice. Each CTA: 32-col strip. g^2 on the fly
//     (clz/ffs) -> exact early-exit vertical min-plus, dt in registers ->
//     strip max -> DSMEM all-to-all + cluster.sync -> normalize + single write.

#define HH 256
#define WW 256
#define NPIX (HH * WW)
#define BIG 512
#define MAXSLICES 64
#define WPR 8
#define SLICE_WORDS (HH * WPR)        // 2048

__device__ unsigned int maskbuf[MAXSLICES * SLICE_WORDS];

// ---------------- Kernel 1: mask pack (R4 version, verbatim) ----------------
#define K1_THREADS 256

__global__ __launch_bounds__(K1_THREADS)
void k1_mask(const float* __restrict__ in) {
    const int slice = blockIdx.x >> 4;
    const int rb    = blockIdx.x & 15;
    const int tid   = threadIdx.x;

    const float4* s4 = reinterpret_cast<const float4*>(in)
                     + (size_t)slice * (NPIX / 4) + (size_t)rb * 1024 + tid * 4;
    float4 a = s4[0], b = s4[1], c = s4[2], d = s4[3];
    unsigned m = 0;
    m |= (a.x != 0.0f) << 0;  m |= (a.y != 0.0f) << 1;
    m |= (a.z != 0.0f) << 2;  m |= (a.w != 0.0f) << 3;
    m |= (b.x != 0.0f) << 4;  m |= (b.y != 0.0f) << 5;
    m |= (b.z != 0.0f) << 6;  m |= (b.w != 0.0f) << 7;
    m |= (c.x != 0.0f) << 8;  m |= (c.y != 0.0f) << 9;
    m |= (c.z != 0.0f) << 10; m |= (c.w != 0.0f) << 11;
    m |= (d.x != 0.0f) << 12; m |= (d.y != 0.0f) << 13;
    m |= (d.z != 0.0f) << 14; m |= (d.w != 0.0f) << 15;
    unsigned other = __shfl_xor_sync(0xffffffffu, m, 1);
    if ((tid & 1) == 0) {
        maskbuf[slice * SLICE_WORDS + rb * 128 + (tid >> 1)] = m | (other << 16);
    }
}

// ---------------- Kernel 2: cluster-fused pass B + normalize ----------------
#define K2_THREADS 512
#define K2_COLS 32
#define PXT 16                         // (256*32)/512 pixels per thread

__global__ __launch_bounds__(K2_THREADS, 2) __cluster_dims__(8, 1, 1)
void k2_fused(float* __restrict__ out) {
    __shared__ unsigned int M[SLICE_WORDS];        // 8 KB slice bitmask
    __shared__ unsigned int g2t[HH * K2_COLS];     // 32 KB g^2 tile [row][col]
    __shared__ float warp_red[K2_THREADS / 32];
    __shared__ float strip_max[8];                 // slot j written by cluster rank j

    const int slice = blockIdx.x >> 3;             // 8 strips per slice
    const int st    = blockIdx.x & 7;              // == cluster rank
    const int c0    = st * K2_COLS;
    const int tid   = threadIdx.x;

    // ---- load slice bitmask (L2-hot): 4 words/thread ----
    {
        const unsigned int* src = maskbuf + slice * SLICE_WORDS;
        #pragma unroll
        for (int k = 0; k < SLICE_WORDS / K2_THREADS; ++k)
            M[k * K2_THREADS + tid] = src[k * K2_THREADS + tid];
    }
    __syncthreads();

    // ---- g^2 for the strip via clz/ffs (16 px/thread) ----
    #pragma unroll
    for (int it = 0; it < PXT; ++it) {
        int i = it * K2_THREADS + tid;
        int r = i >> 5;
        int w = c0 + (i & 31);
        const unsigned int* Mr = M + r * WPR;
        int ci = w >> 5, b = w & 31;

        int ld = BIG;                                          // nearest zero <= w
        unsigned lmask = (b == 31) ? 0xffffffffu : ((2u << b) - 1u);
        unsigned z = (~Mr[ci]) & lmask;
        if (z) {
            ld = b - (31 - __clz(z));
        } else {
            for (int cj = ci - 1; cj >= 0; --cj) {
                unsigned zz = ~Mr[cj];
                if (zz) { ld = (ci - cj) * 32 + b - (31 - __clz(zz)); break; }
            }
        }
        int rd = BIG;                                          // nearest zero >= w
        z = (~Mr[ci]) >> b;
        if (z) {
            rd = __ffs(z) - 1;
        } else {
            for (int cj = ci + 1; cj < WPR; ++cj) {
                unsigned zz = ~Mr[cj];
                if (zz) { rd = cj * 32 + (__ffs(zz) - 1) - w; break; }
            }
        }
        int g = min(min(ld, rd), BIG);
        g2t[r * K2_COLS + (i & 31)] = (unsigned)(g * g);
    }
    __syncthreads();

    // ---- exact vertical min-plus, dt in registers ----
    const float wts[3] = {0.5f, 1.0f, 2.0f};
    const float wc = wts[slice % 3];

    float dt[PXT];
    float lmax = 0.0f;
    #pragma unroll
    for (int it = 0; it < PXT; ++it) {
        int i = it * K2_THREADS + tid;
        int r = i >> 5, c = i & 31;
        int best = (int)g2t[r * K2_COLS + c];
        for (int d = 1; d < HH; ++d) {
            int dd = d * d;
            if (dd >= best) break;                 // exact: candidates >= d^2
            int up = r - d, dn = r + d;
            if (up >= 0) best = min(best, (int)g2t[up * K2_COLS + c] + dd);
            if (dn < HH) best = min(best, (int)g2t[dn * K2_COLS + c] + dd);
        }
        float v = wc * sqrtf((float)best);
        dt[it] = v;
        lmax = fmaxf(lmax, v);
    }

    // ---- strip max (block reduce) ----
    #pragma unroll
    for (int o = 16; o; o >>= 1) lmax = fmaxf(lmax, __shfl_xor_sync(0xffffffffu, lmax, o));
    if ((tid & 31) == 0) warp_red[tid >> 5] = lmax;
    __syncthreads();
    if (tid < 16) {
        float v = warp_red[tid];
        #pragma unroll
        for (int o = 8; o; o >>= 1) v = fmaxf(v, __shfl_xor_sync(0x0000ffffu, v, o, 16));
        if (tid == 0) {
            // broadcast my strip max into slot `st` of every cluster CTA's smem
            unsigned int laddr;
            asm("{ .reg .u64 t; cvta.to.shared.u64 t, %1; cvt.u32.u64 %0, t; }"
                : "=r"(laddr) : "l"(&strip_max[st]));
            #pragma unroll
            for (int peer = 0; peer < 8; ++peer) {
                asm volatile(
                    "{ .reg .b32 ra;\n\t"
                    "mapa.shared::cluster.u32 ra, %0, %1;\n\t"
                    "st.shared::cluster.f32 [ra], %2; }"
                    :: "r"(laddr), "r"(peer), "f"(v) : "memory");
            }
        }
    }

    // ---- single HW cluster barrier: all strip maxima visible everywhere ----
    asm volatile("barrier.cluster.arrive.aligned;" ::: "memory");
    asm volatile("barrier.cluster.wait.aligned;"   ::: "memory");

    // ---- slice max + normalize + single output write ----
    float mx = strip_max[0];
    #pragma unroll
    for (int j = 1; j < 8; ++j) mx = fmaxf(mx, strip_max[j]);
    const float inv = (mx > 0.0f) ? (1.0f / mx) : 0.0f;   // mx==0 -> dt==0 -> out 0

    float* dst = out + (size_t)slice * NPIX;
    #pragma unroll
    for (int it = 0; it < PXT; ++it) {
        int i = it * K2_THREADS + tid;
        int r = i >> 5, c = i & 31;
        dst[r * WW + c0 + c] = (mx - dt[it]) * inv;
    }
}

extern "C" void kernel_launch(void* const* d_in, const int* in_sizes, int n_in,
                              void* d_out, int out_size) {
    const float* in = (const float*)d_in[0];
    float* out = (float*)d_out;
    const int nslices = in_sizes[0] / NPIX;        // 48 for [16,3,256,256]

    k1_mask <<<nslices * 16, K1_THREADS>>>(in);
    k2_fused<<<nslices * 8,  K2_THREADS>>>(out);
}

// round 9
// speedup vs baseline: 1.6944x; 1.6944x over previous
#include <cuda_runtime.h>

// WeightedDistanceTransform — 3-kernel pipeline (R7 structure; k1/k3 MLP x2).
// k1: bitmask pack, 32 px -> 8 independent float4 loads per thread (MLP 8)
// k2: g^2 on the fly (clz/ffs) + exact early-exit vertical min-plus (verbatim R7)
// k3: inverted normalize, 8 float4 load+store pairs per thread.

#define HH 256
#define WW 256
#define NPIX (HH * WW)
#define BIG 512
#define MAXSLICES 64
#define WPR 8
#define SLICE_WORDS (HH * WPR)        // 2048

__device__ unsigned int maskbuf[MAXSLICES * SLICE_WORDS];
__device__ unsigned int mx_bits[MAXSLICES];

// ---------------- Kernel 1: mask pack (R4 pattern, 2 units/thread) ----------------
#define K1_THREADS 256

__global__ __launch_bounds__(K1_THREADS)
void k1_mask(const float* __restrict__ in) {
    // grid = nslices * 8; CTA covers 32 rows = 8192 px
    const int slice = blockIdx.x >> 3;
    const int rb    = blockIdx.x & 7;
    const int tid   = threadIdx.x;

    if (rb == 0 && tid == 0) mx_bits[slice] = 0u;        // reset before k2

    const float4* base = reinterpret_cast<const float4*>(in)
                       + (size_t)slice * (NPIX / 4) + (size_t)rb * 2048;
    const float4* sA = base + tid * 4;                    // unit A: 16 px
    const float4* sB = base + 1024 + tid * 4;             // unit B: 16 px

    // issue all 8 loads back-to-back (MLP 8)
    float4 a0 = sA[0], a1 = sA[1], a2 = sA[2], a3 = sA[3];
    float4 b0 = sB[0], b1 = sB[1], b2 = sB[2], b3 = sB[3];

    unsigned mA = 0, mB = 0;
    mA |= (a0.x != 0.0f) << 0;  mA |= (a0.y != 0.0f) << 1;
    mA |= (a0.z != 0.0f) << 2;  mA |= (a0.w != 0.0f) << 3;
    mA |= (a1.x != 0.0f) << 4;  mA |= (a1.y != 0.0f) << 5;
    mA |= (a1.z != 0.0f) << 6;  mA |= (a1.w != 0.0f) << 7;
    mA |= (a2.x != 0.0f) << 8;  mA |= (a2.y != 0.0f) << 9;
    mA |= (a2.z != 0.0f) << 10; mA |= (a2.w != 0.0f) << 11;
    mA |= (a3.x != 0.0f) << 12; mA |= (a3.y != 0.0f) << 13;
    mA |= (a3.z != 0.0f) << 14; mA |= (a3.w != 0.0f) << 15;

    mB |= (b0.x != 0.0f) << 0;  mB |= (b0.y != 0.0f) << 1;
    mB |= (b0.z != 0.0f) << 2;  mB |= (b0.w != 0.0f) << 3;
    mB |= (b1.x != 0.0f) << 4;  mB |= (b1.y != 0.0f) << 5;
    mB |= (b1.z != 0.0f) << 6;  mB |= (b1.w != 0.0f) << 7;
    mB |= (b2.x != 0.0f) << 8;  mB |= (b2.y != 0.0f) << 9;
    mB |= (b2.z != 0.0f) << 10; mB |= (b2.w != 0.0f) << 11;
    mB |= (b3.x != 0.0f) << 12; mB |= (b3.y != 0.0f) << 13;
    mB |= (b3.z != 0.0f) << 14; mB |= (b3.w != 0.0f) << 15;

    unsigned oA = __shfl_xor_sync(0xffffffffu, mA, 1);
    unsigned oB = __shfl_xor_sync(0xffffffffu, mB, 1);
    if ((tid & 1) == 0) {
        unsigned int* wb = maskbuf + slice * SLICE_WORDS + rb * 256;
        wb[tid >> 1]       = mA | (oA << 16);
        wb[128 + (tid >> 1)] = mB | (oB << 16);
    }
}

// ---------------- Kernel 2: g^2 on the fly + vertical min-plus (verbatim R7) ----------------
#define K2_COLS 16
#define K2_THREADS 512

__global__ __launch_bounds__(K2_THREADS)
void k2_passB(float* __restrict__ out) {
    __shared__ unsigned int M[SLICE_WORDS];       // 8 KB: whole-slice bitmask
    __shared__ unsigned int g2[HH * K2_COLS];     // 16 KB: g^2 tile [row][col]
    __shared__ float red[K2_THREADS / 32];        // 16 warps

    const int slice = blockIdx.x >> 4;            // 16 strips per slice
    const int st    = blockIdx.x & 15;
    const int c0    = st * K2_COLS;
    const int tid   = threadIdx.x;

    {
        const unsigned int* src = maskbuf + slice * SLICE_WORDS;
        #pragma unroll
        for (int k = 0; k < SLICE_WORDS / K2_THREADS; ++k)
            M[k * K2_THREADS + tid] = src[k * K2_THREADS + tid];
    }
    __syncthreads();

    #pragma unroll
    for (int it = 0; it < (HH * K2_COLS) / K2_THREADS; ++it) {
        int i = it * K2_THREADS + tid;
        int r = i >> 4;
        int w = c0 + (i & 15);
        const unsigned int* Mr = M + r * WPR;
        int ci = w >> 5, b = w & 31;

        int ld = BIG;                                          // nearest zero <= w
        unsigned lmask = (b == 31) ? 0xffffffffu : ((2u << b) - 1u);
        unsigned z = (~Mr[ci]) & lmask;
        if (z) {
            ld = b - (31 - __clz(z));
        } else {
            for (int cj = ci - 1; cj >= 0; --cj) {
                unsigned zz = ~Mr[cj];
                if (zz) { ld = (ci - cj) * 32 + b - (31 - __clz(zz)); break; }
            }
        }
        int rd = BIG;                                          // nearest zero >= w
        z = (~Mr[ci]) >> b;
        if (z) {
            rd = __ffs(z) - 1;
        } else {
            for (int cj = ci + 1; cj < WPR; ++cj) {
                unsigned zz = ~Mr[cj];
                if (zz) { rd = cj * 32 + (__ffs(zz) - 1) - w; break; }
            }
        }
        int g = min(min(ld, rd), BIG);
        g2[r * K2_COLS + (i & 15)] = (unsigned)(g * g);
    }
    __syncthreads();

    const float wts[3] = {0.5f, 1.0f, 2.0f};
    const float wc = wts[slice % 3];
    float* dst = out + (size_t)slice * NPIX;

    float lmax = 0.0f;
    #pragma unroll
    for (int it = 0; it < (HH * K2_COLS) / K2_THREADS; ++it) {
        int i = it * K2_THREADS + tid;
        int r = i >> 4, c = i & 15;
        int best = (int)g2[r * K2_COLS + c];
        for (int d = 1; d < HH; ++d) {
            int dd = d * d;
            if (dd >= best) break;                // exact: candidates are >= d^2
            int up = r - d, dn = r + d;
            if (up >= 0) best = min(best, (int)g2[up * K2_COLS + c] + dd);
            if (dn < HH) best = min(best, (int)g2[dn * K2_COLS + c] + dd);
        }
        float dt = wc * sqrtf((float)best);
        dst[r * WW + c0 + c] = dt;
        lmax = fmaxf(lmax, dt);
    }

    #pragma unroll
    for (int o = 16; o; o >>= 1) lmax = fmaxf(lmax, __shfl_xor_sync(0xffffffffu, lmax, o));
    if ((tid & 31) == 0) red[tid >> 5] = lmax;
    __syncthreads();
    if (tid < 16) {
        float v = red[tid];
        #pragma unroll
        for (int o = 8; o; o >>= 1) v = fmaxf(v, __shfl_xor_sync(0x0000ffffu, v, o, 16));
        if (tid == 0) atomicMax(&mx_bits[slice], __float_as_uint(v));  // dt>=0: bit-monotone
    }
}

// ---------------- Kernel 3: normalize (8 float4 pairs/thread) ----------------
#define K3_THREADS 256

__global__ __launch_bounds__(K3_THREADS)
void k3_norm(float* __restrict__ out) {
    const int slice = blockIdx.x >> 3;            // 8 blocks per slice
    const int bl    = blockIdx.x & 7;
    const float mx  = __uint_as_float(mx_bits[slice]);
    const float inv = (mx > 0.0f) ? (1.0f / mx) : 0.0f;   // mx==0 -> dt==0 -> out 0

    float4* p = reinterpret_cast<float4*>(out) + (size_t)slice * (NPIX / 4) + bl * 2048;

    float4 v[8];
    #pragma unroll
    for (int k = 0; k < 8; ++k) v[k] = p[k * K3_THREADS + threadIdx.x];  // MLP 8
    #pragma unroll
    for (int k = 0; k < 8; ++k) {
        float4 t = v[k];
        t.x = (mx - t.x) * inv;
        t.y = (mx - t.y) * inv;
        t.z = (mx - t.z) * inv;
        t.w = (mx - t.w) * inv;
        p[k * K3_THREADS + threadIdx.x] = t;
    }
}

extern "C" void kernel_launch(void* const* d_in, const int* in_sizes, int n_in,
                              void* d_out, int out_size) {
    const float* in = (const float*)d_in[0];
    float* out = (float*)d_out;
    const int nslices = in_sizes[0] / NPIX;       // 48 for [16,3,256,256]

    k1_mask <<<nslices * 8,  K1_THREADS>>>(in);
    k2_passB<<<nslices * 16, K2_THREADS>>>(out);
    k3_norm <<<nslices * 8,  K3_THREADS>>>(out);
}